// round 1
// baseline (speedup 1.0000x reference)
#include <cuda_runtime.h>
#include <math.h>

typedef unsigned long long ull;

#define NB 128
#define HH 128
#define WW 128

// ---------------- packed fp32x2 helpers (sm_100+) ----------------
__device__ __forceinline__ ull fma2(ull a, ull b, ull c) {
    ull d;
    asm("fma.rn.f32x2 %0, %1, %2, %3;" : "=l"(d) : "l"(a), "l"(b), "l"(c));
    return d;
}
__device__ __forceinline__ ull pack2(float lo, float hi) {
    return ((ull)__float_as_uint(hi) << 32) | (ull)__float_as_uint(lo);
}
__device__ __forceinline__ float sum2(ull v) {
    return __uint_as_float((unsigned)v) + __uint_as_float((unsigned)(v >> 32));
}

// ---------------- scratch (static device arrays; no allocs) ----------------
__device__ float g_h[NB * 2 * HH * WW];    // 16 MB: conv1 output
__device__ float g_feat[NB * 8192];        // pooled features
__device__ float g_fc1[NB * 2048];         // fc1 accumulators (atomics)
__device__ float g_fc2[NB * 1024];         // fc2 accumulators (atomics)

// ---------------- init: zero the atomic accumulators ----------------
__global__ void init_kernel() {
    int i = blockIdx.x * blockDim.x + threadIdx.x;
    if (i < NB * 2048) g_fc1[i] = 0.f;
    if (i < NB * 1024) g_fc2[i] = 0.f;
}

// ---------------- conv1: z=concat(x,mask), 3x3 pad1, 9->2 ch ----------------
__global__ void __launch_bounds__(256) conv1_kernel(
    const float* __restrict__ x, const float* __restrict__ mask,
    const float* __restrict__ w1, const float* __restrict__ b1)
{
    __shared__ float s[9 * 10 * 34];
    __shared__ float ws[162];
    __shared__ float bs[2];
    int n = blockIdx.z;
    int ty0 = blockIdx.y * 8, tx0 = blockIdx.x * 32;
    int tid = threadIdx.y * 32 + threadIdx.x;
    if (tid < 162) ws[tid] = w1[tid];
    if (tid < 2) bs[tid] = b1[tid];
    for (int i = tid; i < 9 * 340; i += 256) {
        int c = i / 340, rem = i % 340;
        int yy = rem / 34, xx = rem % 34;
        int gy = ty0 + yy - 1, gx = tx0 + xx - 1;
        float v = 0.f;
        if (gy >= 0 && gy < HH && gx >= 0 && gx < WW)
            v = (c < 8) ? x[((n * 8 + c) * HH + gy) * WW + gx]
                        : mask[(n * HH + gy) * WW + gx];
        s[i] = v;
    }
    __syncthreads();
    int ty = threadIdx.y, tx = threadIdx.x;
    float a0 = bs[0], a1 = bs[1];
#pragma unroll
    for (int c = 0; c < 9; c++)
#pragma unroll
        for (int ky = 0; ky < 3; ky++)
#pragma unroll
            for (int kx = 0; kx < 3; kx++) {
                float v = s[c * 340 + (ty + ky) * 34 + (tx + kx)];
                a0 += v * ws[(0 * 9 + c) * 9 + ky * 3 + kx];
                a1 += v * ws[(1 * 9 + c) * 9 + ky * 3 + kx];
            }
    int oy = ty0 + ty, ox = tx0 + tx;
    g_h[((n * 2 + 0) * HH + oy) * WW + ox] = a0;
    g_h[((n * 2 + 1) * HH + oy) * WW + ox] = a1;
}

// ---------------- fused DCN stage: one CTA per image ----------------
// offset conv (dil=3, 2->27) + sigmoid + modulated deformable sampling
// + 1x1 conv + ReLU + 2x2 maxpool, all from smem-resident h[n].
__global__ void __launch_bounds__(256) dcn_kernel(
    const float* __restrict__ w_off, const float* __restrict__ w_dcn,
    const float* __restrict__ b_dcn, const float* __restrict__ w2,
    const float* __restrict__ b2)
{
    extern __shared__ float sm[];
    float* hs  = sm;            // 32768 floats (2 x 128 x 128)
    float* wof = sm + 32768;    // 486
    float* wd  = wof + 486;     // 36
    float* w2s = wd + 36;       // 4
    float* bds = w2s + 4;       // 2
    float* b2s = bds + 2;       // 2
    int n = blockIdx.x;
    int tid = threadIdx.x;  // 256

    const float4* src = (const float4*)(g_h + n * 32768);
    float4* dst = (float4*)hs;
    for (int i = tid; i < 8192; i += 256) dst[i] = src[i];
    for (int i = tid; i < 486; i += 256) wof[i] = w_off[i];
    if (tid < 36) wd[tid] = w_dcn[tid];
    if (tid < 4) w2s[tid] = w2[tid];
    if (tid < 2) { bds[tid] = b_dcn[tid]; b2s[tid] = b2[tid]; }
    __syncthreads();

    const ull* wof2 = (const ull*)wof;

#pragma unroll 1
    for (int idx = tid; idx < 4096; idx += 256) {
        int py = idx >> 6, px = idx & 63;
        float m0 = -1e30f, m1 = -1e30f;
#pragma unroll 1
        for (int sub = 0; sub < 4; sub++) {
            int y = py * 2 + (sub >> 1);
            int x = px * 2 + (sub & 1);

            // gather the 18 dilated taps of h around (y,x)
            float t[18];
#pragma unroll
            for (int c = 0; c < 2; c++)
#pragma unroll
                for (int j = 0; j < 9; j++) {
                    int yy = y + (j / 3 - 1) * 3;
                    int xx = x + (j % 3 - 1) * 3;
                    float v = 0.f;
                    if (yy >= 0 && yy < HH && xx >= 0 && xx < WW)
                        v = hs[c * 16384 + yy * 128 + xx];
                    t[c * 9 + j] = v;
                }
            ull t2[9];
#pragma unroll
            for (int p = 0; p < 9; p++) t2[p] = pack2(t[2 * p], t[2 * p + 1]);

            // 27 output channels of the offset conv (packed fp32x2 over K=18)
            float om[27];
#pragma unroll
            for (int ch = 0; ch < 27; ch++) {
                ull acc = 0ull;
#pragma unroll
                for (int p = 0; p < 9; p++) acc = fma2(t2[p], wof2[ch * 9 + p], acc);
                om[ch] = sum2(acc);
            }
            // offset = concat(ox, oy) => offset[i] == om[i]; dy[k]=om[2k], dx[k]=om[2k+1]
            float a0 = bds[0], a1 = bds[1];
#pragma unroll
            for (int k = 0; k < 9; k++) {
                float fy = om[2 * k]     + (float)(y + (k / 3 - 1) * 3);
                float fx = om[2 * k + 1] + (float)(x + (k % 3 - 1) * 3);
                float mmk = 1.f / (1.f + __expf(-om[18 + k]));
                float y0f = floorf(fy), x0f = floorf(fx);
                int iy0 = (int)y0f, ix0 = (int)x0f;
                float ly = fy - y0f, lx = fx - x0f;
                float c00 = (1.f - ly) * (1.f - lx), c01 = (1.f - ly) * lx;
                float c10 = ly * (1.f - lx),         c11 = ly * lx;
                bool vy0 = (iy0 >= 0) && (iy0 < HH);
                bool vy1 = (iy0 + 1 >= 0) && (iy0 + 1 < HH);
                bool vx0 = (ix0 >= 0) && (ix0 < WW);
                bool vx1 = (ix0 + 1 >= 0) && (ix0 + 1 < WW);
                int cy0 = min(max(iy0, 0), HH - 1), cy1 = min(max(iy0 + 1, 0), HH - 1);
                int cx0 = min(max(ix0, 0), WW - 1), cx1 = min(max(ix0 + 1, 0), WW - 1);
#pragma unroll
                for (int c = 0; c < 2; c++) {
                    const float* hb = hs + c * 16384;
                    float v00 = (vy0 && vx0) ? hb[cy0 * 128 + cx0] : 0.f;
                    float v01 = (vy0 && vx1) ? hb[cy0 * 128 + cx1] : 0.f;
                    float v10 = (vy1 && vx0) ? hb[cy1 * 128 + cx0] : 0.f;
                    float v11 = (vy1 && vx1) ? hb[cy1 * 128 + cx1] : 0.f;
                    float sc = (v00 * c00 + v01 * c01 + v10 * c10 + v11 * c11) * mmk;
                    a0 += sc * wd[0 * 18 + c * 9 + k];
                    a1 += sc * wd[1 * 18 + c * 9 + k];
                }
            }
            float o0 = fmaxf(a0 * w2s[0] + a1 * w2s[1] + b2s[0], 0.f);
            float o1 = fmaxf(a0 * w2s[2] + a1 * w2s[3] + b2s[1], 0.f);
            m0 = fmaxf(m0, o0);
            m1 = fmaxf(m1, o1);
        }
        g_feat[n * 8192 + idx]        = m0;   // channel 0
        g_feat[n * 8192 + 4096 + idx] = m1;   // channel 1
    }
}

// ---------------- fc1: (128 x 8192) @ (2048 x 8192)^T, split-K, fp32x2 ----------------
__global__ void __launch_bounds__(256) fc1_kernel(const float* __restrict__ W) {
    __shared__ float As[64 * 32];
    __shared__ float Bs[64 * 32];
    int nb = blockIdx.x, jb = blockIdx.y, kz = blockIdx.z;
    int tid = threadIdx.x;
    int ty = tid >> 4, tx = tid & 15;
    ull acc[4][4];
#pragma unroll
    for (int i = 0; i < 4; i++)
#pragma unroll
        for (int j = 0; j < 4; j++) acc[i][j] = 0ull;
    int r = tid >> 3, c4 = (tid & 7) * 4;
    int kbase = kz * 2048;
    for (int kc = 0; kc < 2048; kc += 32) {
        *(float4*)&As[r * 32 + c4]        = *(const float4*)&g_feat[(nb * 64 + r) * 8192 + kbase + kc + c4];
        *(float4*)&As[(r + 32) * 32 + c4] = *(const float4*)&g_feat[(nb * 64 + r + 32) * 8192 + kbase + kc + c4];
        *(float4*)&Bs[r * 32 + c4]        = *(const float4*)&W[(jb * 64 + r) * 8192 + kbase + kc + c4];
        *(float4*)&Bs[(r + 32) * 32 + c4] = *(const float4*)&W[(jb * 64 + r + 32) * 8192 + kbase + kc + c4];
        __syncthreads();
        const ull* A2 = (const ull*)As;
        const ull* B2 = (const ull*)Bs;
#pragma unroll
        for (int kp0 = 0; kp0 < 16; kp0++) {
            int kp = (kp0 + tx) & 15;  // bank-conflict rotation
            ull a[4], b[4];
#pragma unroll
            for (int i = 0; i < 4; i++) a[i] = A2[(ty * 4 + i) * 16 + kp];
#pragma unroll
            for (int j = 0; j < 4; j++) b[j] = B2[(tx * 4 + j) * 16 + kp];
#pragma unroll
            for (int i = 0; i < 4; i++)
#pragma unroll
                for (int j = 0; j < 4; j++) acc[i][j] = fma2(a[i], b[j], acc[i][j]);
        }
        __syncthreads();
    }
#pragma unroll
    for (int i = 0; i < 4; i++)
#pragma unroll
        for (int j = 0; j < 4; j++)
            atomicAdd(&g_fc1[(nb * 64 + ty * 4 + i) * 2048 + jb * 64 + tx * 4 + j],
                      sum2(acc[i][j]));
}

// ---------------- fc2: relu(fc1+bias) @ (1024 x 2048)^T, split-K ----------------
__global__ void __launch_bounds__(256) fc2_kernel(
    const float* __restrict__ W, const float* __restrict__ fc1_b)
{
    __shared__ float As[64 * 32];
    __shared__ float Bs[64 * 32];
    int nb = blockIdx.x, jb = blockIdx.y, kz = blockIdx.z;
    int tid = threadIdx.x;
    int ty = tid >> 4, tx = tid & 15;
    ull acc[4][4];
#pragma unroll
    for (int i = 0; i < 4; i++)
#pragma unroll
        for (int j = 0; j < 4; j++) acc[i][j] = 0ull;
    int r = tid >> 3, c4 = (tid & 7) * 4;
    int kbase = kz * 512;
    for (int kc = 0; kc < 512; kc += 32) {
        int k0 = kbase + kc + c4;
        float4 bias = *(const float4*)&fc1_b[k0];
        float4 v0 = *(const float4*)&g_fc1[(nb * 64 + r) * 2048 + k0];
        float4 v1 = *(const float4*)&g_fc1[(nb * 64 + r + 32) * 2048 + k0];
        v0.x = fmaxf(v0.x + bias.x, 0.f); v0.y = fmaxf(v0.y + bias.y, 0.f);
        v0.z = fmaxf(v0.z + bias.z, 0.f); v0.w = fmaxf(v0.w + bias.w, 0.f);
        v1.x = fmaxf(v1.x + bias.x, 0.f); v1.y = fmaxf(v1.y + bias.y, 0.f);
        v1.z = fmaxf(v1.z + bias.z, 0.f); v1.w = fmaxf(v1.w + bias.w, 0.f);
        *(float4*)&As[r * 32 + c4]        = v0;
        *(float4*)&As[(r + 32) * 32 + c4] = v1;
        *(float4*)&Bs[r * 32 + c4]        = *(const float4*)&W[(jb * 64 + r) * 2048 + k0];
        *(float4*)&Bs[(r + 32) * 32 + c4] = *(const float4*)&W[(jb * 64 + r + 32) * 2048 + k0];
        __syncthreads();
        const ull* A2 = (const ull*)As;
        const ull* B2 = (const ull*)Bs;
#pragma unroll
        for (int kp0 = 0; kp0 < 16; kp0++) {
            int kp = (kp0 + tx) & 15;
            ull a[4], b[4];
#pragma unroll
            for (int i = 0; i < 4; i++) a[i] = A2[(ty * 4 + i) * 16 + kp];
#pragma unroll
            for (int j = 0; j < 4; j++) b[j] = B2[(tx * 4 + j) * 16 + kp];
#pragma unroll
            for (int i = 0; i < 4; i++)
#pragma unroll
                for (int j = 0; j < 4; j++) acc[i][j] = fma2(a[i], b[j], acc[i][j]);
        }
        __syncthreads();
    }
#pragma unroll
    for (int i = 0; i < 4; i++)
#pragma unroll
        for (int j = 0; j < 4; j++)
            atomicAdd(&g_fc2[(nb * 64 + ty * 4 + i) * 1024 + jb * 64 + tx * 4 + j],
                      sum2(acc[i][j]));
}

// ---------------- final: relu(fc2+bias) @ io_w + sigmoid ----------------
__global__ void __launch_bounds__(256) io_kernel(
    const float* __restrict__ fc2_b, const float* __restrict__ io_w,
    const float* __restrict__ io_b, float* __restrict__ out)
{
    int n = blockIdx.x;
    int tid = threadIdx.x;
    float s = 0.f;
    for (int k = tid; k < 1024; k += 256)
        s += fmaxf(g_fc2[n * 1024 + k] + fc2_b[k], 0.f) * io_w[k];
#pragma unroll
    for (int o = 16; o > 0; o >>= 1) s += __shfl_down_sync(0xffffffffu, s, o);
    __shared__ float red[8];
    if ((tid & 31) == 0) red[tid >> 5] = s;
    __syncthreads();
    if (tid == 0) {
        float t = 0.f;
#pragma unroll
        for (int i = 0; i < 8; i++) t += red[i];
        out[n] = 1.f / (1.f + __expf(-(t + io_b[0])));
    }
}

extern "C" void kernel_launch(void* const* d_in, const int* in_sizes, int n_in,
                              void* d_out, int out_size) {
    const float* mask  = (const float*)d_in[0];
    const float* x     = (const float*)d_in[1];
    const float* w1    = (const float*)d_in[2];
    const float* b1    = (const float*)d_in[3];
    const float* w_off = (const float*)d_in[4];
    const float* w_dcn = (const float*)d_in[5];
    const float* b_dcn = (const float*)d_in[6];
    const float* w2    = (const float*)d_in[7];
    const float* b2    = (const float*)d_in[8];
    const float* fc1_w = (const float*)d_in[9];
    const float* fc1_b = (const float*)d_in[10];
    const float* fc2_w = (const float*)d_in[11];
    const float* fc2_b = (const float*)d_in[12];
    const float* io_w  = (const float*)d_in[13];
    const float* io_b  = (const float*)d_in[14];
    float* out = (float*)d_out;

    init_kernel<<<1024, 256>>>();

    dim3 g1(4, 16, 128), b1d(32, 8);
    conv1_kernel<<<g1, b1d>>>(x, mask, w1, b1);

    size_t smem = 33298 * sizeof(float);  // 133,192 B
    cudaFuncSetAttribute(dcn_kernel, cudaFuncAttributeMaxDynamicSharedMemorySize,
                         (int)(136 * 1024));
    dcn_kernel<<<128, 256, smem>>>(w_off, w_dcn, b_dcn, w2, b2);

    dim3 gf1(2, 32, 4);
    fc1_kernel<<<gf1, 256>>>(fc1_w);
    dim3 gf2(2, 16, 4);
    fc2_kernel<<<gf2, 256>>>(fc2_w, fc1_b);
    io_kernel<<<128, 256>>>(fc2_b, io_w, io_b, out);
}